// round 12
// baseline (speedup 1.0000x reference)
#include <cuda_runtime.h>
#include <math.h>

#define N_PATHS 2048
#define N_STEPS 512
#define N_FWD   40
#define DT_F    (1.0f/512.0f)
#define SHIFT_F 0.02f
// DT^-0.4 / Gamma(0.6) = 2^3.6 / 1.4891922488128176  (pure math constant)
#define SC_CONST 8.142489698f

// ---------------- f32x2 packed helpers (Blackwell FFMA2) ----------------
__device__ __forceinline__ unsigned long long pack2(float a, float b) {
    unsigned long long r;
    asm("mov.b64 %0, {%1, %2};" : "=l"(r) : "f"(a), "f"(b));
    return r;
}
__device__ __forceinline__ void unpack2(unsigned long long v, float& a, float& b) {
    asm("mov.b64 {%0, %1}, %2;" : "=f"(a), "=f"(b) : "l"(v));
}
__device__ __forceinline__ unsigned long long fma2(unsigned long long a,
                                                   unsigned long long b,
                                                   unsigned long long c) {
    unsigned long long d;
    asm("fma.rn.f32x2 %0, %1, %2, %3;" : "=l"(d) : "l"(a), "l"(b), "l"(c));
    return d;
}
__device__ __forceinline__ unsigned long long mul2(unsigned long long a,
                                                   unsigned long long b) {
    unsigned long long d;
    asm("mul.rn.f32x2 %0, %1, %2;" : "=l"(d) : "l"(a), "l"(b));
    return d;
}
__device__ __forceinline__ unsigned long long add2(unsigned long long a,
                                                   unsigned long long b) {
    unsigned long long d;
    asm("add.rn.f32x2 %0, %1, %2;" : "=l"(d) : "l"(a), "l"(b));
    return d;
}

// ---------------- fully fused kernel ------------------------------------------
// Per block: in-block precompute (g taps, s2 scan, vol_scale/mu0) -> conv -> path.
#define PPB 2
#define FUSED_TPB 128
#define PH2T (PPB * N_FWD / 2)             // 40 threads, 2 forwards each

// dynamic smem layout (bytes)
#define OFF_SDZ  0                                        // float4[PPB*512]  16KB
#define OFF_SFBM (OFF_SDZ  + PPB * N_STEPS * 16)          // float4[PPB*512]  16KB
#define OFF_SGP  (OFF_SFBM + PPB * N_STEPS * 16)          // float[520]
#define OFF_SS2  (OFF_SGP  + (N_STEPS + 8) * 4)           // float[512]
#define OFF_SVS  (OFF_SS2  + N_STEPS * 4)                 // float[40]
#define OFF_SOM  (OFF_SVS  + N_FWD * 4)                   // float[40]
#define OFF_SMU  (OFF_SOM  + N_FWD * 4)                   // float[40]
#define OFF_WTOT (OFF_SMU  + N_FWD * 4)                   // float[4]
#define SMEM_BYTES (OFF_WTOT + 16)

__global__ void __launch_bounds__(FUSED_TPB, 6)
fused_kernel(const float4* __restrict__ dz,
             const float*  __restrict__ F0,
             const float*  __restrict__ alphas,
             const float*  __restrict__ rhos,
             const float*  __restrict__ nus,
             const float*  __restrict__ tau,
             const float*  __restrict__ loadings,
             const float*  __restrict__ Lam,
             float* __restrict__ out) {
    extern __shared__ __align__(16) char smem_raw[];
    float4* sdz  = (float4*)(smem_raw + OFF_SDZ);
    float4* sfbm = (float4*)(smem_raw + OFF_SFBM);
    float*  sgp  = (float*) (smem_raw + OFF_SGP);   // sgp[4+k]=g[k], [0..3]=0
    float*  ss2  = (float*) (smem_raw + OFF_SS2);
    float*  svs  = (float*) (smem_raw + OFF_SVS);
    float*  som  = (float*) (smem_raw + OFF_SOM);
    float*  smu  = (float*) (smem_raw + OFF_SMU);
    float*  wtot = (float*) (smem_raw + OFF_WTOT);

    const int tid   = threadIdx.x;
    const int lane  = tid & 31;
    const int wid   = tid >> 5;
    const int pbase = blockIdx.x * PPB;

    // ---- stage A: dz loads, g taps, vol_scale/omega ----
    for (int i = tid; i < PPB * N_STEPS; i += FUSED_TPB)
        sdz[i] = dz[(size_t)pbase * N_STEPS + i];

    // g[k] = ((k+1)^0.6 - k^0.6)/0.6 * SC, cancellation-free:
    // (k+1)^0.6 - k^0.6 = k^0.6 * expm1(0.6*log1p(1/k)).
    #pragma unroll
    for (int i = tid; i < N_STEPS; i += FUSED_TPB) {
        float w;
        if (i == 0) {
            w = 1.0f / 0.6f;
        } else {
            float tf = (float)i;
            w = powf(tf, 0.6f) * expm1f(0.6f * log1pf(1.0f / tf)) * (1.0f / 0.6f);
        }
        sgp[4 + i] = w * SC_CONST;
    }
    if (tid < 4) sgp[tid] = 0.0f;

    if (tid < N_FWD) {
        float f0v = F0[tid];
        float vs  = alphas[tid] * sqrtf(fabsf(f0v + SHIFT_F));
        svs[tid]  = vs;
        som[tid]  = tau[tid] * vs / (1.0f + tau[tid] * f0v);
    }
    __syncthreads();

    // ---- stage B: s2 prefix-scan pieces + mu0 matvec ----
    float a0, c0, c1, c2, c3;
    {
        float g0 = sgp[4 + 4 * tid + 0], g1 = sgp[4 + 4 * tid + 1];
        float g2 = sgp[4 + 4 * tid + 2], g3 = sgp[4 + 4 * tid + 3];
        c0 = g0 * g0;
        c1 = c0 + g1 * g1;
        c2 = c1 + g2 * g2;
        c3 = c2 + g3 * g3;
        float incl = c3;
        #pragma unroll
        for (int o = 1; o < 32; o <<= 1) {
            float nv = __shfl_up_sync(0xffffffffu, incl, o);
            if (lane >= o) incl += nv;
        }
        a0 = incl - c3;                    // exclusive within warp
        if (lane == 31) wtot[wid] = incl;
    }
    if (tid < N_FWD) {
        float acc = 0.0f;
        #pragma unroll 8
        for (int m = 0; m < N_FWD; m++)
            acc += __ldg(&Lam[tid * N_FWD + m]) * som[m];
        smu[tid] = -svs[tid] * acc;
    }
    __syncthreads();

    {
        float off = a0;
        #pragma unroll
        for (int w = 0; w < 3; w++)
            if (wid > w) off += wtot[w];
        ss2[4 * tid + 0] = off + c0;
        ss2[4 * tid + 1] = off + c1;
        ss2[4 * tid + 2] = off + c2;
        ss2[4 * tid + 3] = off + c3;
    }

    // ---------------- phase 1: convolution ----------------
    {
        const int t0 = tid * 4;            // this thread owns t0..t0+3

        unsigned long long accA[PPB][4], accB[PPB][4];
        #pragma unroll
        for (int q = 0; q < PPB; q++)
            #pragma unroll
            for (int j = 0; j < 4; j++) { accA[q][j] = 0ull; accB[q][j] = 0ull; }

        // rolling window w[j] = g[t0 + j - s]
        float4 wv = *(const float4*)&sgp[t0 + 4];
        float w0 = wv.x, w1 = wv.y, w2 = wv.z, w3 = wv.w;

        for (int sb = 0; sb <= t0; sb += 4) {
            float4 gn = *(const float4*)&sgp[t0 - sb];
            #pragma unroll
            for (int i = 0; i < 4; i++) {
                const int s = sb + i;
                unsigned long long gw0 = pack2(w0, w0);
                unsigned long long gw1 = pack2(w1, w1);
                unsigned long long gw2 = pack2(w2, w2);
                unsigned long long gw3 = pack2(w3, w3);
                #pragma unroll
                for (int q = 0; q < PPB; q++) {
                    float4 zv = sdz[q * N_STEPS + s];
                    unsigned long long zA = pack2(zv.x, zv.y);
                    unsigned long long zB = pack2(zv.z, zv.w);
                    accA[q][0] = fma2(gw0, zA, accA[q][0]);
                    accB[q][0] = fma2(gw0, zB, accB[q][0]);
                    accA[q][1] = fma2(gw1, zA, accA[q][1]);
                    accB[q][1] = fma2(gw1, zB, accB[q][1]);
                    accA[q][2] = fma2(gw2, zA, accA[q][2]);
                    accB[q][2] = fma2(gw2, zB, accB[q][2]);
                    accA[q][3] = fma2(gw3, zA, accA[q][3]);
                    accB[q][3] = fma2(gw3, zB, accB[q][3]);
                }
                float gnew = (i == 0) ? gn.w : (i == 1) ? gn.z : (i == 2) ? gn.y : gn.x;
                w3 = w2; w2 = w1; w1 = w0; w0 = gnew;
            }
        }

        #pragma unroll
        for (int q = 0; q < PPB; q++)
            #pragma unroll
            for (int j = 0; j < 4; j++) {
                float a, b, c, d;
                unpack2(accA[q][j], a, b);
                unpack2(accB[q][j], c, d);
                sfbm[q * N_STEPS + t0 + j] = make_float4(a, b, c, d);
            }
    }
    __syncthreads();

    // ---------------- phase 2: packed f32x2, 2 forwards per thread ----------------
    if (tid < PH2T) {
        const int q  = tid / (N_FWD / 2);
        const int jj = tid - q * (N_FWD / 2);
        const int n0 = 2 * jj;
        const int n1 = n0 + 1;
        const int p  = pbase + q;

        const float rh0 = rhos[n0], rh1 = rhos[n1];
        const float nu0 = nus[n0],  nu1 = nus[n1];
        const unsigned long long rhop = pack2(rh0, rh1);
        const unsigned long long nup  = pack2(nu0, nu1);
        const unsigned long long sqp  = pack2(sqrtf(fmaxf(1.0f - rh0 * rh0, 0.0f)),
                                              sqrtf(fmaxf(1.0f - rh1 * rh1, 0.0f)));
        const unsigned long long L0p  = pack2(loadings[n0 * 3 + 0], loadings[n1 * 3 + 0]);
        const unsigned long long L1p  = pack2(loadings[n0 * 3 + 1], loadings[n1 * 3 + 1]);
        const unsigned long long L2p  = pack2(loadings[n0 * 3 + 2], loadings[n1 * 3 + 2]);
        const unsigned long long vsp  = pack2(svs[n0], svs[n1]);
        const unsigned long long mup  = pack2(smu[n0] * DT_F, smu[n1] * DT_F);
        const unsigned long long ncvp = pack2(-0.5f * nu0 * nu0 * DT_F,
                                              -0.5f * nu1 * nu1 * DT_F);
        const float f00 = F0[n0], f01 = F0[n1];

        const float4* fb = sfbm + q * N_STEPS;
        const float4* zp = sdz  + q * N_STEPS;
        float* op = out + (size_t)p * (N_STEPS + 1) * N_FWD + n0;

        unsigned long long accp = pack2(f00, f01);
        __stcs((float2*)op, make_float2(f00, f01));
        op += N_FWD;

        for (int t = 0; t < N_STEPS; t++) {
            float4 f = fb[t];
            float4 z = zp[t];
            float s2v = ss2[t];

            unsigned long long fx = pack2(f.x, f.x);
            unsigned long long fy = pack2(f.y, f.y);
            unsigned long long fz = pack2(f.z, f.z);
            unsigned long long fw = pack2(f.w, f.w);
            unsigned long long zx = pack2(z.x, z.x);
            unsigned long long zy = pack2(z.y, z.y);
            unsigned long long zz = pack2(z.z, z.z);
            unsigned long long s2p = pack2(s2v, s2v);

            unsigned long long crv = fma2(fx, L0p, fma2(fy, L1p, mul2(fz, L2p)));
            unsigned long long fbmp = fma2(rhop, crv, mul2(sqp, fw));
            unsigned long long wrp  = fma2(zx, L0p, fma2(zy, L1p, mul2(zz, L2p)));
            unsigned long long argp = fma2(nup, fbmp, mul2(ncvp, s2p));

            float ar0, ar1;
            unpack2(argp, ar0, ar1);
            float u0 = __expf(ar0);
            float u1 = __expf(ar1);
            unsigned long long up = pack2(u0, u1);

            unsigned long long u2p = mul2(up, up);
            unsigned long long uvp = mul2(up, vsp);
            unsigned long long dfp = fma2(mup, u2p, mul2(wrp, uvp));
            accp = add2(accp, dfp);

            float o0, o1;
            unpack2(accp, o0, o1);
            __stcs((float2*)op, make_float2(o0, o1));
            op += N_FWD;
        }
    }
}

// ---------------- launcher ----------------
extern "C" void kernel_launch(void* const* d_in, const int* in_sizes, int n_in,
                              void* d_out, int out_size) {
    const float* dz       = (const float*)d_in[0];   // (2048, 512, 4)
    const float* F0       = (const float*)d_in[1];   // (40,)
    const float* alphas   = (const float*)d_in[2];   // (40,)
    const float* rhos     = (const float*)d_in[3];   // (40,)
    const float* nus      = (const float*)d_in[4];   // (40,)
    const float* tau      = (const float*)d_in[5];   // (40,)
    const float* loadings = (const float*)d_in[6];   // (40, 3)
    const float* Lam      = (const float*)d_in[7];   // (40, 40)
    float* out = (float*)d_out;                      // (2048, 513, 40)

    fused_kernel<<<N_PATHS / PPB, FUSED_TPB, SMEM_BYTES>>>(
        (const float4*)dz, F0, alphas, rhos, nus, tau, loadings, Lam, out);
}

// round 13
// speedup vs baseline: 1.1011x; 1.1011x over previous
#include <cuda_runtime.h>
#include <math.h>

#define N_PATHS 2048
#define N_STEPS 512
#define N_FWD   40
#define DT_F    (1.0f/512.0f)
#define SHIFT_F 0.02f
// DT^-0.4 / Gamma(0.6) = 2^3.6 / 1.4891922488128176
#define SC_CONST 8.142489698f
// C = SC / Gamma(0.4)
#define C_CONST  (SC_CONST / 2.2181595437576885f)

// ---- sum-of-exponentials quadrature: g[k] ~= sum_m w_m lam_m^k for k >= K0 ----
#define M_SOE 32
#define HQ    1.0f
#define Y0_Q  (-29.5f)
#define K0    8
#define LCH   16
#define NCH   32

// ---------------- device scratch ----------------
__device__ float d_g[N_STEPS];
__device__ float d_s2[N_STEPS];
__device__ float d_vs[N_FWD];
__device__ float d_mu0[N_FWD];
__device__ float d_lam[M_SOE];
__device__ float d_wk[M_SOE];      // w_m * lam^K0
__device__ float d_lamL[M_SOE];    // lam^LCH

// ---------------- f32x2 packed helpers ----------------
__device__ __forceinline__ unsigned long long pack2(float a, float b) {
    unsigned long long r;
    asm("mov.b64 %0, {%1, %2};" : "=l"(r) : "f"(a), "f"(b));
    return r;
}
__device__ __forceinline__ void unpack2(unsigned long long v, float& a, float& b) {
    asm("mov.b64 {%0, %1}, %2;" : "=f"(a), "=f"(b) : "l"(v));
}
__device__ __forceinline__ unsigned long long fma2(unsigned long long a,
                                                   unsigned long long b,
                                                   unsigned long long c) {
    unsigned long long d;
    asm("fma.rn.f32x2 %0, %1, %2, %3;" : "=l"(d) : "l"(a), "l"(b), "l"(c));
    return d;
}

// ---------------- pre_a: taps (8 blocks) + SOE consts + per-n consts (block 8) ----
__global__ void pre_a(const float* __restrict__ F0,
                      const float* __restrict__ alphas,
                      const float* __restrict__ tau,
                      const float* __restrict__ Lam) {
    __shared__ float som[N_FWD];
    __shared__ float svs[N_FWD];
    const int b = blockIdx.x, tid = threadIdx.x;
    if (b < 8) {
        int t = b * 64 + tid;
        float w;
        if (t == 0) {
            w = 1.0f / 0.6f;
        } else {
            float tf = (float)t;
            w = powf(tf, 0.6f) * expm1f(0.6f * log1pf(1.0f / tf)) * (1.0f / 0.6f);
        }
        d_g[t] = w * SC_CONST;
    } else {
        if (tid < M_SOE) {
            float y = Y0_Q + (float)tid * HQ;
            float x = expf(y);
            float lam = expf(-x);
            float w = HQ * C_CONST * expf(-0.6f * y) * (-expm1f(-x));
            float l2 = lam * lam, l4 = l2 * l2, l8 = l4 * l4;
            d_lam[tid]  = lam;
            d_wk[tid]   = w * l8;       // K0 = 8
            d_lamL[tid] = l8 * l8;      // LCH = 16
        }
        if (tid < N_FWD) {
            float f0v = F0[tid];
            float vs  = alphas[tid] * sqrtf(fabsf(f0v + SHIFT_F));
            svs[tid]  = vs;
            d_vs[tid] = vs;
            som[tid]  = tau[tid] * vs / (1.0f + tau[tid] * f0v);
        }
        __syncthreads();
        if (tid < N_FWD) {
            float acc = 0.0f;
            #pragma unroll 8
            for (int m = 0; m < N_FWD; m++)
                acc += Lam[tid * N_FWD + m] * som[m];
            d_mu0[tid] = -svs[tid] * acc;
        }
    }
}

// ---------------- pre_b: prefix sum of g^2 ----------------
__global__ void pre_b() {
    const int t = threadIdx.x, lane = t & 31, w = t >> 5;
    float gv = d_g[t];
    float v = gv * gv;
    #pragma unroll
    for (int o = 1; o < 32; o <<= 1) {
        float nv = __shfl_up_sync(0xffffffffu, v, o);
        if (lane >= o) v += nv;
    }
    __shared__ float wsum[16];
    if (lane == 31) wsum[w] = v;
    __syncthreads();
    if (w == 0 && lane < 16) {
        float s = wsum[lane];
        #pragma unroll
        for (int o = 1; o < 16; o <<= 1) {
            float nv = __shfl_up_sync(0xffffu, s, o);
            if (lane >= o) s += nv;
        }
        wsum[lane] = s;
    }
    __syncthreads();
    d_s2[t] = v + ((w > 0) ? wsum[w - 1] : 0.0f);
}

// ---------------- fused kernel ----------------
#define PPB 2
#define FUSED_TPB 128
#define PH2_THREADS (PPB * N_FWD)

// dynamic smem layout (bytes)
#define OFF_SDZ   0                                        // float4[1024] 16384
#define OFF_SFBM  (OFF_SDZ + 16384)                        // float4[2*32*17] 17408 (padded)
#define OFF_V     (OFF_SFBM + 17408)                       // u64[2*2*32*33] 33792 (padded)
#define OFF_SS2   (OFF_V + 33792)                          // float[512] 2048
#define OFF_LAM   (OFF_SS2 + 2048)                         // float[32]
#define OFF_WK    (OFF_LAM + 128)
#define OFF_LAML  (OFF_WK + 128)
#define OFF_G     (OFF_LAML + 128)                         // float[8]
#define SMEM_BYTES (OFF_G + 32)                            // 70048

__global__ void __launch_bounds__(FUSED_TPB)
fused_kernel(const float4* __restrict__ dz,
             const float*  __restrict__ F0,
             const float*  __restrict__ rhos,
             const float*  __restrict__ nus,
             const float*  __restrict__ loadings,
             float* __restrict__ out) {
    extern __shared__ __align__(16) char smem_raw[];
    float4* sdz4  = (float4*)(smem_raw + OFF_SDZ);
    float4* sfbm4 = (float4*)(smem_raw + OFF_SFBM);
    unsigned long long* VU   = (unsigned long long*)(smem_raw + OFF_V);
    unsigned long long* sdzU = (unsigned long long*)(smem_raw + OFF_SDZ);
    unsigned long long* sfbU = (unsigned long long*)(smem_raw + OFF_SFBM);
    float* ss2   = (float*)(smem_raw + OFF_SS2);
    float* s_lam = (float*)(smem_raw + OFF_LAM);
    float* s_wk  = (float*)(smem_raw + OFF_WK);
    float* s_lamL= (float*)(smem_raw + OFF_LAML);
    float* s_g   = (float*)(smem_raw + OFF_G);

    const int tid   = threadIdx.x;
    const int pbase = blockIdx.x * PPB;

    for (int i = tid; i < PPB * N_STEPS; i += FUSED_TPB)
        sdz4[i] = dz[(size_t)pbase * N_STEPS + i];
    for (int i = tid; i < N_STEPS; i += FUSED_TPB)
        ss2[i] = d_s2[i];
    if (tid < M_SOE) {
        s_lam[tid]  = d_lam[tid];
        s_wk[tid]   = d_wk[tid];
        s_lamL[tid] = d_lamL[tid];
    }
    if (tid < K0) s_g[tid] = d_g[tid];
    __syncthreads();

    // thread map for conv passes: chunk c, channel-pair dp, path q
    const int c  = tid & 31;
    const int dp = (tid >> 5) & 1;
    const int q  = tid >> 6;
    const int tb = c * LCH;
    const int vbase = ((q * 2 + dp) * M_SOE) * 33;

    // delayed stream u[t] = dz[t - K0] for t in chunk, cached in regs
    unsigned long long dzc[LCH];
    #pragma unroll
    for (int i = 0; i < LCH; i++) {
        int gt = tb + i - K0;
        dzc[i] = (gt >= 0) ? sdzU[(q * N_STEPS + gt) * 2 + dp] : 0ull;
    }

    // ---- pass 1: per-chunk local state sums V ----
    #pragma unroll 1
    for (int m = 0; m < M_SOE; m++) {
        float lm = s_lam[m];
        unsigned long long lam2 = pack2(lm, lm);
        unsigned long long S = 0ull;
        #pragma unroll
        for (int i = 0; i < LCH; i++)
            S = fma2(lam2, S, dzc[i]);
        VU[vbase + m * 33 + c] = S;
    }
    __syncthreads();

    // ---- pass 2: sequential carry propagation across chunks (remapped threads) ----
    {
        const int m2  = tid & 31;
        const int dp2 = (tid >> 5) & 1;
        const int q2  = tid >> 6;
        float ll = s_lamL[m2];
        unsigned long long lamL2 = pack2(ll, ll);
        unsigned long long run = 0ull;
        const int base = ((q2 * 2 + dp2) * M_SOE + m2) * 33;
        #pragma unroll 4
        for (int c2 = 0; c2 < NCH; c2++) {
            unsigned long long v = VU[base + c2];
            VU[base + c2] = run;          // now holds carry-in state for chunk c2
            run = fma2(lamL2, run, v);
        }
    }
    __syncthreads();

    // ---- pass 3: near field + mode replay, emit fbm into smem ----
    {
        unsigned long long nc[K0];
        #pragma unroll
        for (int j = 0; j < K0; j++)
            nc[j] = sdzU[(q * N_STEPS + tb + K0 + j) * 2 + dp];

        unsigned long long g2[K0];
        #pragma unroll
        for (int k = 0; k < K0; k++) {
            float gv = s_g[k];
            g2[k] = pack2(gv, gv);
        }

        unsigned long long F[LCH];
        #pragma unroll
        for (int i = 0; i < LCH; i++) {
            unsigned long long acc = 0ull;
            #pragma unroll
            for (int k = 0; k < K0; k++) {
                const int d = i - k;               // in [-7, 15]
                unsigned long long zv = (d <= 7) ? dzc[d + 8] : nc[d - 8];
                acc = fma2(g2[k], zv, acc);
            }
            F[i] = acc;
        }

        #pragma unroll 1
        for (int m = 0; m < M_SOE; m++) {
            float lm = s_lam[m], wm = s_wk[m];
            unsigned long long lam2 = pack2(lm, lm);
            unsigned long long wk2  = pack2(wm, wm);
            unsigned long long S = VU[vbase + m * 33 + c];
            #pragma unroll
            for (int i = 0; i < LCH; i++) {
                S = fma2(lam2, S, dzc[i]);
                F[i] = fma2(wk2, S, F[i]);
            }
        }

        #pragma unroll
        for (int i = 0; i < LCH; i++)
            sfbU[(q * (NCH * 17) + c * 17 + i) * 2 + dp] = F[i];
    }
    __syncthreads();

    // ---- phase 2: mix / exp / dF / cumsum / store (R10 form) ----
    if (tid < PH2_THREADS) {
        const int qq = tid / N_FWD;
        const int n  = tid - qq * N_FWD;
        const int p  = pbase + qq;

        const float rho = rhos[n];
        const float nu  = nus[n];
        const float sq  = sqrtf(fmaxf(1.0f - rho * rho, 0.0f));
        const float l0  = loadings[n * 3 + 0];
        const float l1  = loadings[n * 3 + 1];
        const float l2  = loadings[n * 3 + 2];
        const float vs   = d_vs[n];
        const float muDT = d_mu0[n] * DT_F;
        const float cvar = 0.5f * nu * nu * DT_F;
        const float f0   = F0[n];

        float* op = out + (size_t)p * (N_STEPS + 1) * N_FWD + n;

        float acc = f0;
        __stcs(op, f0);
        op += N_FWD;

        for (int t = 0; t < N_STEPS; t++) {
            const int cc = t >> 4, ii = t & 15;
            float4 f = sfbm4[qq * (NCH * 17) + cc * 17 + ii];
            float4 z = sdz4[qq * N_STEPS + t];
            float fbm_curve = f.x * l0 + f.y * l1 + f.z * l2;
            float fbm = rho * fbm_curve + sq * f.w;
            float wr  = z.x * l0 + z.y * l1 + z.z * l2;
            float u   = __expf(nu * fbm - cvar * ss2[t]);
            acc += muDT * (u * u) + wr * (u * vs);
            __stcs(op, acc);
            op += N_FWD;
        }
    }
}

// ---------------- launcher ----------------
extern "C" void kernel_launch(void* const* d_in, const int* in_sizes, int n_in,
                              void* d_out, int out_size) {
    const float* dz       = (const float*)d_in[0];
    const float* F0       = (const float*)d_in[1];
    const float* alphas   = (const float*)d_in[2];
    const float* rhos     = (const float*)d_in[3];
    const float* nus      = (const float*)d_in[4];
    const float* tau      = (const float*)d_in[5];
    const float* loadings = (const float*)d_in[6];
    const float* Lam      = (const float*)d_in[7];
    float* out = (float*)d_out;

    cudaFuncSetAttribute(fused_kernel,
                         cudaFuncAttributeMaxDynamicSharedMemorySize, SMEM_BYTES);

    pre_a<<<9, 64>>>(F0, alphas, tau, Lam);
    pre_b<<<1, N_STEPS>>>();
    fused_kernel<<<N_PATHS / PPB, FUSED_TPB, SMEM_BYTES>>>(
        (const float4*)dz, F0, rhos, nus, loadings, out);
}